// round 4
// baseline (speedup 1.0000x reference)
#include <cuda_runtime.h>
#include <math.h>

#define MAX_NODES 200000
#define HID 512
#define GDIM 128

// Scratch (allocation-free rule: __device__ globals).
// g_H is reused: K1 writes Hi, K2 consumes it, K3 overwrites with Hj.
__device__ float g_H [(size_t)MAX_NODES * HID];   // Hi, then Hj
__device__ float g_Gi[(size_t)MAX_NODES * GDIM];  // pre-sigmoid i-gate logits

__global__ void zero_kernel(float* p, int n) {
    int i = blockIdx.x * blockDim.x + threadIdx.x;
    if (i < n) p[i] = 0.0f;
}

// Tiled SGEMM: C[M,N] = epilogue(A[M,K] * B[K,N] + bias)
// A is row-major with row stride lda. For k >= Ksplit the loader switches to A2
// (same lda) with column k-Ksplit — implements concat([h_T, h_0]) without
// materializing X. Tiles never straddle Ksplit (both multiples of 16).
// MODE 0: C = relu(.)       MODE 1: C = (.)
// MODE 2: v = sigmoid(gate[row,n]) * (.); segmented-sum v over sorted gidx
//         within each thread's 8 consecutive rows; atomicAdd runs into Rout.
template<int MODE>
__global__ __launch_bounds__(256, 2)
void gemm_k(const float* __restrict__ A, const float* __restrict__ A2,
            int lda, int Ksplit,
            const float* __restrict__ B, const float* __restrict__ bias,
            float* __restrict__ C,
            const float* __restrict__ gate,
            const int* __restrict__ gidx,          // graph_index is int32 (JAX x64 off)
            float* __restrict__ Rout,
            int M, int N, int K)
{
    __shared__ float As[16][128];  // transposed: As[k][m]
    __shared__ float Bs[16][128];  // Bs[k][n]

    const int tid = threadIdx.x;
    const int tx = tid & 15;        // n-direction, 16 threads
    const int ty = tid >> 4;        // m-direction, 16 threads
    const int m0 = blockIdx.y * 128;
    const int n0 = blockIdx.x * 128;
    const int tm = ty * 8;
    const int tn = tx * 8;

    float acc[8][8];
#pragma unroll
    for (int i = 0; i < 8; i++)
#pragma unroll
        for (int j = 0; j < 8; j++) acc[i][j] = 0.0f;

    for (int k0 = 0; k0 < K; k0 += 16) {
        const float* Asrc = (k0 < Ksplit) ? A : A2;
        const int kb = (k0 < Ksplit) ? k0 : (k0 - Ksplit);

        // Load A tile (128 rows x 16 k), 512 float4 slots, 2 per thread
#pragma unroll
        for (int l = 0; l < 2; l++) {
            int idx = tid + l * 256;
            int r  = idx >> 2;          // 0..127
            int kk = (idx & 3) << 2;    // 0,4,8,12
            float4 v = make_float4(0.f, 0.f, 0.f, 0.f);
            int row = m0 + r;
            if (row < M)
                v = *reinterpret_cast<const float4*>(Asrc + (size_t)row * lda + kb + kk);
            As[kk + 0][r] = v.x;
            As[kk + 1][r] = v.y;
            As[kk + 2][r] = v.z;
            As[kk + 3][r] = v.w;
        }
        // Load B tile (16 k x 128 n)
#pragma unroll
        for (int l = 0; l < 2; l++) {
            int idx = tid + l * 256;
            int r = idx >> 5;           // 0..15
            int c = (idx & 31) << 2;    // 0..124
            float4 v = *reinterpret_cast<const float4*>(B + (size_t)(k0 + r) * N + n0 + c);
            *reinterpret_cast<float4*>(&Bs[r][c]) = v;
        }
        __syncthreads();

#pragma unroll
        for (int k = 0; k < 16; k++) {
            float a[8], b[8];
#pragma unroll
            for (int i = 0; i < 8; i++) a[i] = As[k][tm + i];
#pragma unroll
            for (int j = 0; j < 8; j++) b[j] = Bs[k][tn + j];
#pragma unroll
            for (int i = 0; i < 8; i++)
#pragma unroll
                for (int j = 0; j < 8; j++)
                    acc[i][j] = fmaf(a[i], b[j], acc[i][j]);
        }
        __syncthreads();
    }

    float br[8];
#pragma unroll
    for (int j = 0; j < 8; j++) br[j] = bias[n0 + tn + j];

    if (MODE == 0 || MODE == 1) {
#pragma unroll
        for (int i = 0; i < 8; i++) {
            int row = m0 + tm + i;
            if (row >= M) continue;
            float o[8];
#pragma unroll
            for (int j = 0; j < 8; j++) {
                float v = acc[i][j] + br[j];
                if (MODE == 0) v = fmaxf(v, 0.0f);
                o[j] = v;
            }
            float* cp = C + (size_t)row * N + n0 + tn;
            *reinterpret_cast<float4*>(cp)     = make_float4(o[0], o[1], o[2], o[3]);
            *reinterpret_cast<float4*>(cp + 4) = make_float4(o[4], o[5], o[6], o[7]);
        }
    } else {
        // MODE 2: gated product + segmented reduce over 8 consecutive rows
        int cur = -1;
        float run[8];
#pragma unroll
        for (int j = 0; j < 8; j++) run[j] = 0.0f;

        for (int i = 0; i < 8; i++) {
            int row = m0 + tm + i;
            if (row >= M) break;
            int g = gidx[row];
            if (g != cur) {
                if (cur >= 0) {
#pragma unroll
                    for (int j = 0; j < 8; j++)
                        atomicAdd(&Rout[(size_t)cur * N + n0 + tn + j], run[j]);
                }
                cur = g;
#pragma unroll
                for (int j = 0; j < 8; j++) run[j] = 0.0f;
            }
#pragma unroll
            for (int j = 0; j < 8; j++) {
                float gt = gate[(size_t)row * GDIM + n0 + tn + j];
                float sg = 1.0f / (1.0f + __expf(-gt));
                run[j] += sg * (acc[i][j] + br[j]);
            }
        }
        if (cur >= 0) {
#pragma unroll
            for (int j = 0; j < 8; j++)
                atomicAdd(&Rout[(size_t)cur * N + n0 + tn + j], run[j]);
        }
    }
}

extern "C" void kernel_launch(void* const* d_in, const int* in_sizes, int n_in,
                              void* d_out, int out_size)
{
    const float* h_T  = (const float*)d_in[0];
    const float* h_0  = (const float*)d_in[1];
    const int*   gidx = (const int*)d_in[2];     // int32 (JAX default x64 disabled)
    const float* Wi1  = (const float*)d_in[3];
    const float* bi1  = (const float*)d_in[4];
    const float* Wi2  = (const float*)d_in[5];
    const float* bi2  = (const float*)d_in[6];
    const float* Wj1  = (const float*)d_in[7];
    const float* bj1  = (const float*)d_in[8];
    const float* Wj2  = (const float*)d_in[9];
    const float* bj2  = (const float*)d_in[10];
    float* R = (float*)d_out;

    const int M = in_sizes[0] / 128;   // n_node
    const int mtiles = (M + 127) / 128;

    float *H, *Gi;
    cudaGetSymbolAddress((void**)&H,  g_H);
    cudaGetSymbolAddress((void**)&Gi, g_Gi);

    // Output is poisoned; zero it (graph replays re-zero every iteration).
    zero_kernel<<<(out_size + 255) / 256, 256>>>(R, out_size);

    // K1: Hi = relu([h_T | h_0] Wi1 + bi1)   [M,512] = [M,256][256,512]
    gemm_k<0><<<dim3(4, mtiles), 256>>>(h_T, h_0, 128, 128, Wi1, bi1, H,
                                        nullptr, nullptr, nullptr, M, 512, 256);
    // K2: Gi = Hi Wi2 + bi2                   [M,128] = [M,512][512,128]
    gemm_k<1><<<dim3(1, mtiles), 256>>>(H, H, 512, 512, Wi2, bi2, Gi,
                                        nullptr, nullptr, nullptr, M, 128, 512);
    // K3: Hj = relu(h_T Wj1 + bj1) (reuses H buffer; Hi is dead after K2)
    gemm_k<0><<<dim3(4, mtiles), 256>>>(h_T, h_T, 128, 128, Wj1, bj1, H,
                                        nullptr, nullptr, nullptr, M, 512, 128);
    // K4: R += segsum(sigmoid(Gi) * (Hj Wj2 + bj2))
    gemm_k<2><<<dim3(1, mtiles), 256>>>(H, H, 512, 512, Wj2, bj2, nullptr,
                                        Gi, gidx, R, M, 128, 512);
}

// round 7
// speedup vs baseline: 2.1355x; 2.1355x over previous
#include <cuda_runtime.h>
#include <cuda_bf16.h>
#include <cstdint>
#include <math.h>

#define MAX_NODES 200000
#define HID 512
#define GDIM 128

// ---------------------------------------------------------------------------
// Scratch (__device__ globals; allocation-free rule)
// ---------------------------------------------------------------------------
__device__ __nv_bfloat16 g_Hhi[(size_t)MAX_NODES * HID];
__device__ __nv_bfloat16 g_Hlo[(size_t)MAX_NODES * HID];
__device__ float         g_Gi [(size_t)MAX_NODES * GDIM];

// Pre-transposed, hi/lo-split weights: Wt[n][k] = W[k][n]
__device__ __nv_bfloat16 g_Wi1hi[512 * 256], g_Wi1lo[512 * 256];
__device__ __nv_bfloat16 g_Wi2hi[128 * 512], g_Wi2lo[128 * 512];
__device__ __nv_bfloat16 g_Wj1hi[512 * 128], g_Wj1lo[512 * 128];
__device__ __nv_bfloat16 g_Wj2hi[128 * 512], g_Wj2lo[128 * 512];

// ---------------------------------------------------------------------------
__device__ __forceinline__ uint32_t smem_to_u32(const void* p) {
    uint32_t a;
    asm("{ .reg .u64 t; cvta.to.shared.u64 t, %1; cvt.u32.u64 %0, t; }" : "=r"(a) : "l"(p));
    return a;
}
// SW64 swizzle for 64-byte rows (8 rows x 64B atom)
#define SWZ64(o) ((o) ^ (((o) >> 3) & 0x30))

__device__ __forceinline__ void ldmatrix_x4(uint32_t& r0, uint32_t& r1,
                                            uint32_t& r2, uint32_t& r3, uint32_t addr) {
    asm volatile("ldmatrix.sync.aligned.m8n8.x4.shared.b16 {%0,%1,%2,%3}, [%4];"
                 : "=r"(r0), "=r"(r1), "=r"(r2), "=r"(r3) : "r"(addr));
}

__device__ __forceinline__ void mma_bf16(float* d, uint32_t a0, uint32_t a1,
                                         uint32_t a2, uint32_t a3,
                                         uint32_t b0, uint32_t b1) {
    asm volatile(
        "mma.sync.aligned.m16n8k16.row.col.f32.bf16.bf16.f32 "
        "{%0,%1,%2,%3}, {%4,%5,%6,%7}, {%8,%9}, {%0,%1,%2,%3};"
        : "+f"(d[0]), "+f"(d[1]), "+f"(d[2]), "+f"(d[3])
        : "r"(a0), "r"(a1), "r"(a2), "r"(a3), "r"(b0), "r"(b1));
}

// ---------------------------------------------------------------------------
__global__ void zero_kernel(float* p, int n) {
    int i = blockIdx.x * blockDim.x + threadIdx.x;
    if (i < n) p[i] = 0.0f;
}

// Wt[n][k] = W[k][n], split into bf16 hi/lo
__global__ void transpose_split(const float* __restrict__ W,
                                __nv_bfloat16* __restrict__ Thi,
                                __nv_bfloat16* __restrict__ Tlo, int K, int N) {
    int idx = blockIdx.x * blockDim.x + threadIdx.x;
    if (idx >= K * N) return;
    int k = idx / N, n = idx % N;
    float x = W[idx];
    __nv_bfloat16 h = __float2bfloat16_rn(x);
    float lo = x - __bfloat162float(h);
    Thi[(size_t)n * K + k] = h;
    Tlo[(size_t)n * K + k] = __float2bfloat16_rn(lo);
}

// ---------------------------------------------------------------------------
// HMMA GEMM: C[M,N] = epi(A * B^T + bias)
// A: hi/lo split bf16. B: pre-transposed split weights [N][K].
// Split product: Ahi*Bhi + Ahi*Blo + Alo*Bhi (lo*lo dropped, ~1e-5 rel).
// ASRC 0: A built on the fly from fp32 [Af1 | Af2] concat at Ksplit.
// ASRC 1: A read from bf16 pair (Ahi/Alo).
// MODE 0: C = relu(.)  -> split bf16 Chi/Clo
// MODE 1: C = (.)      -> fp32 Cf
// MODE 2: v = sigmoid(gate)*(.); per-CTA segmented sum over sorted gidx -> atomicAdd
//
// CTA: 128x128 tile, 8 warps (2 M x 4 N), warp = 64x32, K-chunk = 32, 2 stages.
// ---------------------------------------------------------------------------
#define STAGE_SZ   32768                       // Ah(8K) Al(8K) Bh(8K) Bl(8K)
#define SMEM_DYN   (1024 + 128 * 132 * 4)      // pad + max(2 stages, Dts) = 68608
// (2*STAGE_SZ = 65536 < 128*132*4 = 67584)

template<int MODE, int ASRC>
__global__ __launch_bounds__(256, 2)
void mlp_mma(const float* __restrict__ Af1, const float* __restrict__ Af2,
             int lda_f, int Ksplit,
             const __nv_bfloat16* __restrict__ Ahi, const __nv_bfloat16* __restrict__ Alo,
             int lda_b,
             const __nv_bfloat16* __restrict__ Bhi, const __nv_bfloat16* __restrict__ Blo,
             const float* __restrict__ bias,
             __nv_bfloat16* __restrict__ Chi, __nv_bfloat16* __restrict__ Clo, int ldc,
             float* __restrict__ Cf,
             const float* __restrict__ gate, const int* __restrict__ gidx,
             float* __restrict__ Rout,
             int M, int N, int K)
{
    extern __shared__ char smem_raw[];
    const uint32_t sb = smem_to_u32(smem_raw);
    const uint32_t base = (sb + 1023) & ~1023u;      // 512B-align for swizzle
    char* basep = smem_raw + (base - sb);

    const int tid  = threadIdx.x;
    const int wid  = tid >> 5;
    const int lane = tid & 31;
    const int wm = wid & 1;          // 2 warp-rows of 64
    const int wn = wid >> 1;         // 4 warp-cols of 32
    const int m0 = blockIdx.y * 128;
    const int n0 = blockIdx.x * 128;

    const int lr = lane & 7;         // ldmatrix row-within-tile
    const int q  = lane >> 3;        // ldmatrix quadrant

    float acc[4][4][4];
#pragma unroll
    for (int a = 0; a < 4; a++)
#pragma unroll
        for (int b = 0; b < 4; b++)
#pragma unroll
            for (int d = 0; d < 4; d++) acc[a][b][d] = 0.0f;

    const int NC = K >> 5;
    for (int c = 0; c < NC; c++) {
        const int st = c & 1;
        char* sp = basep + st * STAGE_SZ;
        const uint32_t su = base + st * STAGE_SZ;
        const int k0 = c << 5;

        // ---------- load A tile [128 x 32] hi/lo ----------
        if (ASRC == 0) {
            const float* src = (k0 < Ksplit) ? Af1 : Af2;
            const int kb = (k0 < Ksplit) ? k0 : (k0 - Ksplit);
#pragma unroll
            for (int i = 0; i < 4; i++) {
                int idx = tid + (i << 8);        // 1024 float4 slots
                int r = idx >> 3, c4 = idx & 7;
                float4 v = make_float4(0.f, 0.f, 0.f, 0.f);
                if (m0 + r < M)
                    v = *reinterpret_cast<const float4*>(src + (size_t)(m0 + r) * lda_f + kb + (c4 << 2));
                __nv_bfloat16 h0 = __float2bfloat16_rn(v.x);
                __nv_bfloat16 h1 = __float2bfloat16_rn(v.y);
                __nv_bfloat16 h2 = __float2bfloat16_rn(v.z);
                __nv_bfloat16 h3 = __float2bfloat16_rn(v.w);
                __nv_bfloat16 l0 = __float2bfloat16_rn(v.x - __bfloat162float(h0));
                __nv_bfloat16 l1 = __float2bfloat16_rn(v.y - __bfloat162float(h1));
                __nv_bfloat16 l2 = __float2bfloat16_rn(v.z - __bfloat162float(h2));
                __nv_bfloat16 l3 = __float2bfloat16_rn(v.w - __bfloat162float(h3));
                uint32_t o = SWZ64((r << 6) + (c4 << 3));
                *reinterpret_cast<__nv_bfloat162*>(sp + o)            = __halves2bfloat162(h0, h1);
                *reinterpret_cast<__nv_bfloat162*>(sp + o + 4)        = __halves2bfloat162(h2, h3);
                *reinterpret_cast<__nv_bfloat162*>(sp + 8192 + o)     = __halves2bfloat162(l0, l1);
                *reinterpret_cast<__nv_bfloat162*>(sp + 8192 + o + 4) = __halves2bfloat162(l2, l3);
            }
        } else {
#pragma unroll
            for (int i = 0; i < 2; i++) {
                int idx = tid + (i << 8);        // 512 uint4 per buffer
                int r = idx >> 2, c16 = idx & 3;
                uint4 vh = make_uint4(0, 0, 0, 0), vl = make_uint4(0, 0, 0, 0);
                if (m0 + r < M) {
                    size_t e = (size_t)(m0 + r) * lda_b + k0 + (c16 << 3);
                    vh = *reinterpret_cast<const uint4*>(Ahi + e);
                    vl = *reinterpret_cast<const uint4*>(Alo + e);
                }
                uint32_t o = SWZ64((r << 6) + (c16 << 4));
                *reinterpret_cast<uint4*>(sp + o)        = vh;
                *reinterpret_cast<uint4*>(sp + 8192 + o) = vl;
            }
        }
        // ---------- load B tile [128 x 32] hi/lo ----------
#pragma unroll
        for (int i = 0; i < 2; i++) {
            int idx = tid + (i << 8);
            int r = idx >> 2, c16 = idx & 3;
            size_t e = (size_t)(n0 + r) * K + k0 + (c16 << 3);
            uint32_t o = SWZ64((r << 6) + (c16 << 4));
            *reinterpret_cast<uint4*>(sp + 16384 + o) = *reinterpret_cast<const uint4*>(Bhi + e);
            *reinterpret_cast<uint4*>(sp + 24576 + o) = *reinterpret_cast<const uint4*>(Blo + e);
        }

        __syncthreads();

        // ---------- compute: 2 k16 steps ----------
        const uint32_t Ah = su, Al = su + 8192, Bh = su + 16384, Bl = su + 24576;
#pragma unroll
        for (int s = 0; s < 2; s++) {
            const int bc = s << 5;               // k16 step byte base
            // B fragments: 2 x ldmatrix.x4, each covers two n8 tiles
            uint32_t bhf[8], blf[8];
#pragma unroll
            for (int p = 0; p < 2; p++) {
                int nrow = (wn << 5) + (p << 4) + ((q >> 1) << 3) + lr;
                uint32_t o = SWZ64((nrow << 6) + bc + ((q & 1) << 4));
                ldmatrix_x4(bhf[p * 4 + 0], bhf[p * 4 + 1], bhf[p * 4 + 2], bhf[p * 4 + 3], Bh + o);
                ldmatrix_x4(blf[p * 4 + 0], blf[p * 4 + 1], blf[p * 4 + 2], blf[p * 4 + 3], Bl + o);
            }
#pragma unroll
            for (int mt = 0; mt < 4; mt++) {
                int mrow = (wm << 6) + (mt << 4) + ((q & 1) << 3) + lr;
                uint32_t o = SWZ64((mrow << 6) + bc + ((q >> 1) << 4));
                uint32_t ah0, ah1, ah2, ah3, al0, al1, al2, al3;
                ldmatrix_x4(ah0, ah1, ah2, ah3, Ah + o);
                ldmatrix_x4(al0, al1, al2, al3, Al + o);
#pragma unroll
                for (int nt = 0; nt < 4; nt++) {
                    int bi = (nt >> 1) * 4 + (nt & 1) * 2;
                    uint32_t b0h = bhf[bi], b1h = bhf[bi + 1];
                    uint32_t b0l = blf[bi], b1l = blf[bi + 1];
                    mma_bf16(acc[mt][nt], ah0, ah1, ah2, ah3, b0h, b1h);
                    mma_bf16(acc[mt][nt], ah0, ah1, ah2, ah3, b0l, b1l);
                    mma_bf16(acc[mt][nt], al0, al1, al2, al3, b0h, b1h);
                }
            }
        }
        __syncthreads();
    }

    // ---------------- epilogue ----------------
    const int g = lane >> 2, tig = lane & 3;

    if (MODE == 0 || MODE == 1) {
#pragma unroll
        for (int mt = 0; mt < 4; mt++) {
#pragma unroll
            for (int hf = 0; hf < 2; hf++) {
                int row = m0 + (wm << 6) + (mt << 4) + g + (hf << 3);
                if (row >= M) continue;
#pragma unroll
                for (int nt = 0; nt < 4; nt++) {
                    int col = n0 + (wn << 5) + (nt << 3) + (tig << 1);
                    float v0 = acc[mt][nt][hf * 2 + 0] + __ldg(bias + col);
                    float v1 = acc[mt][nt][hf * 2 + 1] + __ldg(bias + col + 1);
                    if (MODE == 0) {
                        v0 = fmaxf(v0, 0.0f);
                        v1 = fmaxf(v1, 0.0f);
                        __nv_bfloat16 h0 = __float2bfloat16_rn(v0);
                        __nv_bfloat16 h1 = __float2bfloat16_rn(v1);
                        __nv_bfloat16 l0 = __float2bfloat16_rn(v0 - __bfloat162float(h0));
                        __nv_bfloat16 l1 = __float2bfloat16_rn(v1 - __bfloat162float(h1));
                        *reinterpret_cast<__nv_bfloat162*>(Chi + (size_t)row * ldc + col) = __halves2bfloat162(h0, h1);
                        *reinterpret_cast<__nv_bfloat162*>(Clo + (size_t)row * ldc + col) = __halves2bfloat162(l0, l1);
                    } else {
                        *reinterpret_cast<float2*>(Cf + (size_t)row * ldc + col) = make_float2(v0, v1);
                    }
                }
            }
        }
    } else {
        // MODE 2: gated values -> SMEM (stride 132), then segmented scan + atomics
        float* Dts = reinterpret_cast<float*>(basep);
#pragma unroll
        for (int mt = 0; mt < 4; mt++) {
#pragma unroll
            for (int hf = 0; hf < 2; hf++) {
                int lrow = (wm << 6) + (mt << 4) + g + (hf << 3);
                int row = m0 + lrow;
                if (row >= M) continue;
#pragma unroll
                for (int nt = 0; nt < 4; nt++) {
                    int col = (wn << 5) + (nt << 3) + (tig << 1);
                    float v0 = acc[mt][nt][hf * 2 + 0] + __ldg(bias + col);
                    float v1 = acc[mt][nt][hf * 2 + 1] + __ldg(bias + col + 1);
                    float g0 = __ldg(gate + (size_t)row * GDIM + col);
                    float g1 = __ldg(gate + (size_t)row * GDIM + col + 1);
                    float s0 = 1.0f / (1.0f + __expf(-g0));
                    float s1 = 1.0f / (1.0f + __expf(-g1));
                    *reinterpret_cast<float2*>(Dts + lrow * 132 + col) = make_float2(s0 * v0, s1 * v1);
                }
            }
        }
        __syncthreads();

        const int tx = tid & 15, ty = tid >> 4;
        const int tm = ty * 8, tn = tx * 8;
        int cur = -1;
        float run[8];
#pragma unroll
        for (int j = 0; j < 8; j++) run[j] = 0.0f;
        for (int i = 0; i < 8; i++) {
            int r = m0 + tm + i;
            if (r >= M) break;
            int gg = gidx[r];
            if (gg != cur) {
                if (cur >= 0) {
#pragma unroll
                    for (int j = 0; j < 8; j++)
                        atomicAdd(&Rout[(size_t)cur * GDIM + tn + j], run[j]);
                }
                cur = gg;
#pragma unroll
                for (int j = 0; j < 8; j++) run[j] = 0.0f;
            }
#pragma unroll
            for (int j = 0; j < 8; j++)
                run[j] += Dts[(tm + i) * 132 + tn + j];
        }
        if (cur >= 0) {
#pragma unroll
            for (int j = 0; j < 8; j++)
                atomicAdd(&Rout[(size_t)cur * GDIM + tn + j], run[j]);
        }
    }
}

// ---------------------------------------------------------------------------
extern "C" void kernel_launch(void* const* d_in, const int* in_sizes, int n_in,
                              void* d_out, int out_size)
{
    const float* h_T  = (const float*)d_in[0];
    const float* h_0  = (const float*)d_in[1];
    const int*   gidx = (const int*)d_in[2];     // int32 (JAX x64 disabled)
    const float* Wi1  = (const float*)d_in[3];
    const float* bi1  = (const float*)d_in[4];
    const float* Wi2  = (const float*)d_in[5];
    const float* bi2  = (const float*)d_in[6];
    const float* Wj1  = (const float*)d_in[7];
    const float* bj1  = (const float*)d_in[8];
    const float* Wj2  = (const float*)d_in[9];
    const float* bj2  = (const float*)d_in[10];
    float* R = (float*)d_out;

    const int M = in_sizes[0] / 128;
    const int mt = (M + 127) / 128;

    __nv_bfloat16 *Hhi, *Hlo, *Wi1h, *Wi1l, *Wi2h, *Wi2l, *Wj1h, *Wj1l, *Wj2h, *Wj2l;
    float* Gi;
    cudaGetSymbolAddress((void**)&Hhi, g_Hhi);
    cudaGetSymbolAddress((void**)&Hlo, g_Hlo);
    cudaGetSymbolAddress((void**)&Gi,  g_Gi);
    cudaGetSymbolAddress((void**)&Wi1h, g_Wi1hi); cudaGetSymbolAddress((void**)&Wi1l, g_Wi1lo);
    cudaGetSymbolAddress((void**)&Wi2h, g_Wi2hi); cudaGetSymbolAddress((void**)&Wi2l, g_Wi2lo);
    cudaGetSymbolAddress((void**)&Wj1h, g_Wj1hi); cudaGetSymbolAddress((void**)&Wj1l, g_Wj1lo);
    cudaGetSymbolAddress((void**)&Wj2h, g_Wj2hi); cudaGetSymbolAddress((void**)&Wj2l, g_Wj2lo);

    cudaFuncSetAttribute(mlp_mma<0,0>, cudaFuncAttributeMaxDynamicSharedMemorySize, SMEM_DYN);
    cudaFuncSetAttribute(mlp_mma<1,1>, cudaFuncAttributeMaxDynamicSharedMemorySize, SMEM_DYN);
    cudaFuncSetAttribute(mlp_mma<2,1>, cudaFuncAttributeMaxDynamicSharedMemorySize, SMEM_DYN);

    // weight prep (tiny) + output zero
    transpose_split<<<(256 * 512 + 255) / 256, 256>>>(Wi1, Wi1h, Wi1l, 256, 512);
    transpose_split<<<(512 * 128 + 255) / 256, 256>>>(Wi2, Wi2h, Wi2l, 512, 128);
    transpose_split<<<(128 * 512 + 255) / 256, 256>>>(Wj1, Wj1h, Wj1l, 128, 512);
    transpose_split<<<(512 * 128 + 255) / 256, 256>>>(Wj2, Wj2h, Wj2l, 512, 128);
    zero_kernel<<<(out_size + 255) / 256, 256>>>(R, out_size);

    // K1: H = relu([h_T|h_0] Wi1 + bi1), written as split bf16
    mlp_mma<0,0><<<dim3(4, mt), 256, SMEM_DYN>>>(
        h_T, h_0, 128, 128, nullptr, nullptr, 0, Wi1h, Wi1l, bi1,
        Hhi, Hlo, HID, nullptr, nullptr, nullptr, nullptr, M, 512, 256);

    // K2: Gi = H Wi2 + bi2 (fp32 gate logits)
    mlp_mma<1,1><<<dim3(1, mt), 256, SMEM_DYN>>>(
        nullptr, nullptr, 0, 0, Hhi, Hlo, HID, Wi2h, Wi2l, bi2,
        nullptr, nullptr, GDIM, Gi, nullptr, nullptr, nullptr, M, 128, 512);

    // K3: H = relu(h_T Wj1 + bj1)  (reuses H buffers)
    mlp_mma<0,0><<<dim3(4, mt), 256, SMEM_DYN>>>(
        h_T, h_T, 128, 128, nullptr, nullptr, 0, Wj1h, Wj1l, bj1,
        Hhi, Hlo, HID, nullptr, nullptr, nullptr, nullptr, M, 512, 128);

    // K4: R += segsum(sigmoid(Gi) * (H Wj2 + bj2))
    mlp_mma<2,1><<<dim3(1, mt), 256, SMEM_DYN>>>(
        nullptr, nullptr, 0, 0, Hhi, Hlo, HID, Wj2h, Wj2l, bj2,
        nullptr, nullptr, 0, nullptr, Gi, gidx, R, M, 128, 512);
}

// round 8
// speedup vs baseline: 4.0702x; 1.9060x over previous
#include <cuda_runtime.h>
#include <cuda_fp16.h>
#include <cstdint>
#include <math.h>

#define MAX_NODES 200000
#define HID 512
#define GDIM 128

// ---------------------------------------------------------------------------
// Scratch (__device__ globals; allocation-free rule)
// ---------------------------------------------------------------------------
__device__ __align__(16) __half g_hT16[(size_t)MAX_NODES * 128];
__device__ __align__(16) __half g_h016[(size_t)MAX_NODES * 128];
__device__ __align__(16) __half g_H16 [(size_t)MAX_NODES * HID];
__device__ float g_Gi[(size_t)MAX_NODES * GDIM];

// Pre-transposed fp16 weights: Wt[n][k] = W[k][n]
__device__ __align__(16) __half g_Wi1t[512 * 256];
__device__ __align__(16) __half g_Wi2t[128 * 512];
__device__ __align__(16) __half g_Wj1t[512 * 128];
__device__ __align__(16) __half g_Wj2t[128 * 512];

// ---------------------------------------------------------------------------
__device__ __forceinline__ uint32_t smem_to_u32(const void* p) {
    uint32_t a;
    asm("{ .reg .u64 t; cvta.to.shared.u64 t, %1; cvt.u32.u64 %0, t; }" : "=r"(a) : "l"(p));
    return a;
}
// SW64 swizzle for 64-byte rows (8 rows x 64B atom)
#define SWZ64(o) ((o) ^ (((o) >> 3) & 0x30))

__device__ __forceinline__ void ldmatrix_x4(uint32_t& r0, uint32_t& r1,
                                            uint32_t& r2, uint32_t& r3, uint32_t addr) {
    asm volatile("ldmatrix.sync.aligned.m8n8.x4.shared.b16 {%0,%1,%2,%3}, [%4];"
                 : "=r"(r0), "=r"(r1), "=r"(r2), "=r"(r3) : "r"(addr));
}

__device__ __forceinline__ void mma_fp16(float* d, uint32_t a0, uint32_t a1,
                                         uint32_t a2, uint32_t a3,
                                         uint32_t b0, uint32_t b1) {
    asm volatile(
        "mma.sync.aligned.m16n8k16.row.col.f32.f16.f16.f32 "
        "{%0,%1,%2,%3}, {%4,%5,%6,%7}, {%8,%9}, {%0,%1,%2,%3};"
        : "+f"(d[0]), "+f"(d[1]), "+f"(d[2]), "+f"(d[3])
        : "r"(a0), "r"(a1), "r"(a2), "r"(a3), "r"(b0), "r"(b1));
}

__device__ __forceinline__ void cp16(uint32_t saddr, const void* g, bool ok) {
    int sz = ok ? 16 : 0;
    asm volatile("cp.async.ca.shared.global [%0], [%1], 16, %2;"
                 :: "r"(saddr), "l"(g), "r"(sz));
}
#define CP_COMMIT()  asm volatile("cp.async.commit_group;" ::: "memory")
#define CP_WAIT(N)   asm volatile("cp.async.wait_group %0;" :: "n"(N) : "memory")

// ---------------------------------------------------------------------------
__global__ void zero_kernel(float* p, int n) {
    int i = blockIdx.x * blockDim.x + threadIdx.x;
    if (i < n) p[i] = 0.0f;
}

// fp32 -> fp16 bulk convert (n divisible by 4)
__global__ void convert16(const float* __restrict__ in, __half* __restrict__ out, int n4) {
    int i = blockIdx.x * blockDim.x + threadIdx.x;
    if (i >= n4) return;
    float4 v = reinterpret_cast<const float4*>(in)[i];
    __half2 a = __halves2half2(__float2half_rn(v.x), __float2half_rn(v.y));
    __half2 b = __halves2half2(__float2half_rn(v.z), __float2half_rn(v.w));
    reinterpret_cast<__half2*>(out)[2 * i]     = a;
    reinterpret_cast<__half2*>(out)[2 * i + 1] = b;
}

// Wt[n][k] = fp16(W[k][n])
__global__ void transpose16(const float* __restrict__ W, __half* __restrict__ T, int K, int N) {
    int idx = blockIdx.x * blockDim.x + threadIdx.x;
    if (idx >= K * N) return;
    int k = idx / N, n = idx % N;
    T[(size_t)n * K + k] = __float2half_rn(W[idx]);
}

// ---------------------------------------------------------------------------
// fp16 HMMA GEMM: C[M,N] = epi(A * B^T + bias)
// A: fp16 [Af1 | Af2] concat at Ksplit (row stride lda). B: fp16 [N][K].
// MODE 0: C = relu(.) -> fp16 Ch
// MODE 1: C = (.)     -> fp32 Cf
// MODE 2: v = sigmoid(gate)*(.); per-CTA segmented sum over sorted gidx -> atomicAdd
// CTA: 128x128 tile, 8 warps (2M x 4N), warp 64x32, K-chunk 32, 3-stage cp.async.
// ---------------------------------------------------------------------------
#define STAGE_SZ 16384                        // A(8K) + B(8K)
#define SMEM_DYN (1024 + 128 * 132 * 4)       // pad + max(3 stages 48K, Dts 66K)

template<int MODE>
__global__ __launch_bounds__(256, 2)
void mlp_mma(const __half* __restrict__ Af1, const __half* __restrict__ Af2,
             int lda, int Ksplit,
             const __half* __restrict__ B, const float* __restrict__ bias,
             __half* __restrict__ Ch, int ldc,
             float* __restrict__ Cf,
             const float* __restrict__ gate, const int* __restrict__ gidx,
             float* __restrict__ Rout,
             int M, int N, int K)
{
    extern __shared__ char smem_raw[];
    const uint32_t sb = smem_to_u32(smem_raw);
    const uint32_t base = (sb + 1023) & ~1023u;
    char* basep = smem_raw + (base - sb);

    const int tid  = threadIdx.x;
    const int wid  = tid >> 5;
    const int lane = tid & 31;
    const int wm = wid & 1;
    const int wn = wid >> 1;
    const int m0 = blockIdx.y * 128;
    const int n0 = blockIdx.x * 128;

    const int lr = lane & 7;
    const int q  = lane >> 3;

    float acc[4][4][4];
#pragma unroll
    for (int a = 0; a < 4; a++)
#pragma unroll
        for (int b = 0; b < 4; b++)
#pragma unroll
            for (int d = 0; d < 4; d++) acc[a][b][d] = 0.0f;

    const int NC = K >> 5;

    // loader lambda: issue cp.async for chunk c into stage (c % 3)
    auto load_stage = [&](int c) {
        const uint32_t su = base + (c % 3) * STAGE_SZ;
        const int k0 = c << 5;
        const __half* Asrc = (k0 < Ksplit) ? Af1 : Af2;
        const int kb = (k0 < Ksplit) ? k0 : (k0 - Ksplit);
#pragma unroll
        for (int i = 0; i < 2; i++) {
            int idx = tid + (i << 8);           // 512 x 16B = A tile
            int r = idx >> 2, c16 = idx & 3;
            int row = m0 + r;
            bool ok = row < M;
            if (!ok) row = m0;                  // clamp to valid address
            cp16(su + SWZ64((r << 6) + (c16 << 4)),
                 Asrc + (size_t)row * lda + kb + (c16 << 3), ok);
        }
#pragma unroll
        for (int i = 0; i < 2; i++) {
            int idx = tid + (i << 8);           // B tile
            int r = idx >> 2, c16 = idx & 3;
            cp16(su + 8192 + SWZ64((r << 6) + (c16 << 4)),
                 B + (size_t)(n0 + r) * K + k0 + (c16 << 3), true);
        }
        CP_COMMIT();
    };

    load_stage(0);
    load_stage(1);

    for (int c = 0; c < NC; c++) {
        if (c + 1 < NC) { CP_WAIT(1); } else { CP_WAIT(0); }
        __syncthreads();
        if (c + 2 < NC) load_stage(c + 2);

        const uint32_t su = base + (c % 3) * STAGE_SZ;
        const uint32_t As = su, Bs = su + 8192;
#pragma unroll
        for (int s = 0; s < 2; s++) {
            const int bc = s << 5;
            uint32_t bf[8];
#pragma unroll
            for (int p = 0; p < 2; p++) {
                int nrow = (wn << 5) + (p << 4) + ((q >> 1) << 3) + lr;
                uint32_t o = SWZ64((nrow << 6) + bc + ((q & 1) << 4));
                ldmatrix_x4(bf[p * 4 + 0], bf[p * 4 + 1], bf[p * 4 + 2], bf[p * 4 + 3], Bs + o);
            }
#pragma unroll
            for (int mt = 0; mt < 4; mt++) {
                int mrow = (wm << 6) + (mt << 4) + ((q & 1) << 3) + lr;
                uint32_t o = SWZ64((mrow << 6) + bc + ((q >> 1) << 4));
                uint32_t a0, a1, a2, a3;
                ldmatrix_x4(a0, a1, a2, a3, As + o);
#pragma unroll
                for (int nt = 0; nt < 4; nt++) {
                    int bi = (nt >> 1) * 4 + (nt & 1) * 2;
                    mma_fp16(acc[mt][nt], a0, a1, a2, a3, bf[bi], bf[bi + 1]);
                }
            }
        }
    }

    // ---------------- epilogue ----------------
    const int g = lane >> 2, tig = lane & 3;

    if (MODE == 0 || MODE == 1) {
#pragma unroll
        for (int mt = 0; mt < 4; mt++) {
#pragma unroll
            for (int hf = 0; hf < 2; hf++) {
                int row = m0 + (wm << 6) + (mt << 4) + g + (hf << 3);
                if (row >= M) continue;
#pragma unroll
                for (int nt = 0; nt < 4; nt++) {
                    int col = n0 + (wn << 5) + (nt << 3) + (tig << 1);
                    float v0 = acc[mt][nt][hf * 2 + 0] + __ldg(bias + col);
                    float v1 = acc[mt][nt][hf * 2 + 1] + __ldg(bias + col + 1);
                    if (MODE == 0) {
                        v0 = fmaxf(v0, 0.0f);
                        v1 = fmaxf(v1, 0.0f);
                        *reinterpret_cast<__half2*>(Ch + (size_t)row * ldc + col) =
                            __halves2half2(__float2half_rn(v0), __float2half_rn(v1));
                    } else {
                        *reinterpret_cast<float2*>(Cf + (size_t)row * ldc + col) = make_float2(v0, v1);
                    }
                }
            }
        }
    } else {
        __syncthreads();   // stages dead; reuse smem for Dts
        float* Dts = reinterpret_cast<float*>(basep);
#pragma unroll
        for (int mt = 0; mt < 4; mt++) {
#pragma unroll
            for (int hf = 0; hf < 2; hf++) {
                int lrow = (wm << 6) + (mt << 4) + g + (hf << 3);
                int row = m0 + lrow;
                if (row >= M) continue;
#pragma unroll
                for (int nt = 0; nt < 4; nt++) {
                    int col = (wn << 5) + (nt << 3) + (tig << 1);
                    float v0 = acc[mt][nt][hf * 2 + 0] + __ldg(bias + col);
                    float v1 = acc[mt][nt][hf * 2 + 1] + __ldg(bias + col + 1);
                    float g0 = __ldg(gate + (size_t)row * GDIM + col);
                    float g1 = __ldg(gate + (size_t)row * GDIM + col + 1);
                    float s0 = 1.0f / (1.0f + __expf(-g0));
                    float s1 = 1.0f / (1.0f + __expf(-g1));
                    *reinterpret_cast<float2*>(Dts + lrow * 132 + col) = make_float2(s0 * v0, s1 * v1);
                }
            }
        }
        __syncthreads();

        const int tx = tid & 15, ty = tid >> 4;
        const int tm = ty * 8, tn = tx * 8;
        int cur = -1;
        float run[8];
#pragma unroll
        for (int j = 0; j < 8; j++) run[j] = 0.0f;
        for (int i = 0; i < 8; i++) {
            int r = m0 + tm + i;
            if (r >= M) break;
            int gg = gidx[r];
            if (gg != cur) {
                if (cur >= 0) {
#pragma unroll
                    for (int j = 0; j < 8; j++)
                        atomicAdd(&Rout[(size_t)cur * GDIM + tn + j], run[j]);
                }
                cur = gg;
#pragma unroll
                for (int j = 0; j < 8; j++) run[j] = 0.0f;
            }
#pragma unroll
            for (int j = 0; j < 8; j++)
                run[j] += Dts[(tm + i) * 132 + tn + j];
        }
        if (cur >= 0) {
#pragma unroll
            for (int j = 0; j < 8; j++)
                atomicAdd(&Rout[(size_t)cur * GDIM + tn + j], run[j]);
        }
    }
}

// ---------------------------------------------------------------------------
extern "C" void kernel_launch(void* const* d_in, const int* in_sizes, int n_in,
                              void* d_out, int out_size)
{
    const float* h_T  = (const float*)d_in[0];
    const float* h_0  = (const float*)d_in[1];
    const int*   gidx = (const int*)d_in[2];     // int32 (JAX x64 disabled)
    const float* Wi1  = (const float*)d_in[3];
    const float* bi1  = (const float*)d_in[4];
    const float* Wi2  = (const float*)d_in[5];
    const float* bi2  = (const float*)d_in[6];
    const float* Wj1  = (const float*)d_in[7];
    const float* bj1  = (const float*)d_in[8];
    const float* Wj2  = (const float*)d_in[9];
    const float* bj2  = (const float*)d_in[10];
    float* R = (float*)d_out;

    const int M = in_sizes[0] / 128;
    const int mt = (M + 127) / 128;

    __half *hT16, *h016, *H16, *Wi1t, *Wi2t, *Wj1t, *Wj2t;
    float* Gi;
    cudaGetSymbolAddress((void**)&hT16, g_hT16);
    cudaGetSymbolAddress((void**)&h016, g_h016);
    cudaGetSymbolAddress((void**)&H16,  g_H16);
    cudaGetSymbolAddress((void**)&Gi,   g_Gi);
    cudaGetSymbolAddress((void**)&Wi1t, g_Wi1t);
    cudaGetSymbolAddress((void**)&Wi2t, g_Wi2t);
    cudaGetSymbolAddress((void**)&Wj1t, g_Wj1t);
    cudaGetSymbolAddress((void**)&Wj2t, g_Wj2t);

    cudaFuncSetAttribute(mlp_mma<0>, cudaFuncAttributeMaxDynamicSharedMemorySize, SMEM_DYN);
    cudaFuncSetAttribute(mlp_mma<1>, cudaFuncAttributeMaxDynamicSharedMemorySize, SMEM_DYN);
    cudaFuncSetAttribute(mlp_mma<2>, cudaFuncAttributeMaxDynamicSharedMemorySize, SMEM_DYN);

    // prep: fp16 conversions, weight transposes, output zero
    int n4 = (M * 128) / 4;
    convert16<<<(n4 + 255) / 256, 256>>>(h_T, hT16, n4);
    convert16<<<(n4 + 255) / 256, 256>>>(h_0, h016, n4);
    transpose16<<<(256 * 512 + 255) / 256, 256>>>(Wi1, Wi1t, 256, 512);
    transpose16<<<(512 * 128 + 255) / 256, 256>>>(Wi2, Wi2t, 512, 128);
    transpose16<<<(128 * 512 + 255) / 256, 256>>>(Wj1, Wj1t, 128, 512);
    transpose16<<<(512 * 128 + 255) / 256, 256>>>(Wj2, Wj2t, 512, 128);
    zero_kernel<<<(out_size + 255) / 256, 256>>>(R, out_size);

    // K1: H = relu([h_T|h_0] Wi1 + bi1) -> fp16
    mlp_mma<0><<<dim3(4, mt), 256, SMEM_DYN>>>(
        hT16, h016, 128, 128, Wi1t, bi1, H16, HID,
        nullptr, nullptr, nullptr, nullptr, M, 512, 256);

    // K2: Gi = H Wi2 + bi2 (fp32 gate logits)
    mlp_mma<1><<<dim3(1, mt), 256, SMEM_DYN>>>(
        H16, H16, HID, 1 << 20, Wi2t, bi2, nullptr, GDIM,
        Gi, nullptr, nullptr, nullptr, M, 128, 512);

    // K3: H = relu(h_T Wj1 + bj1) -> fp16 (reuses H buffer)
    mlp_mma<0><<<dim3(4, mt), 256, SMEM_DYN>>>(
        hT16, hT16, 128, 1 << 20, Wj1t, bj1, H16, HID,
        nullptr, nullptr, nullptr, nullptr, M, 512, 128);

    // K4: R += segsum(sigmoid(Gi) * (H Wj2 + bj2))
    mlp_mma<2><<<dim3(1, mt), 256, SMEM_DYN>>>(
        H16, H16, HID, 1 << 20, Wj2t, bj2, nullptr, 0,
        nullptr, Gi, gidx, R, M, 128, 512);
}

// round 11
// speedup vs baseline: 4.5178x; 1.1100x over previous
#include <cuda_runtime.h>
#include <cuda_fp16.h>
#include <cstdint>
#include <math.h>

#define MAX_NODES 200000
#define GDIM 128

// ---------------------------------------------------------------------------
// Scratch (__device__ globals; allocation-free rule)
// ---------------------------------------------------------------------------
__device__ float g_Gi[(size_t)MAX_NODES * GDIM];

// Pre-transposed fp16 weights: Wt[n][k] = W[k][n]
__device__ __align__(16) __half g_Wi1t[512 * 256];
__device__ __align__(16) __half g_Wi2t[128 * 512];
__device__ __align__(16) __half g_Wj1t[512 * 128];
__device__ __align__(16) __half g_Wj2t[128 * 512];

// ---------------------------------------------------------------------------
__device__ __forceinline__ uint32_t smem_to_u32(const void* p) {
    uint32_t a;
    asm("{ .reg .u64 t; cvta.to.shared.u64 t, %1; cvt.u32.u64 %0, t; }" : "=r"(a) : "l"(p));
    return a;
}
// SW64 swizzle for 64-byte rows (8 rows x 64B atom)
#define SWZ64(o) ((o) ^ (((o) >> 3) & 0x30))

__device__ __forceinline__ void ldmatrix_x4(uint32_t& r0, uint32_t& r1,
                                            uint32_t& r2, uint32_t& r3, uint32_t addr) {
    asm volatile("ldmatrix.sync.aligned.m8n8.x4.shared.b16 {%0,%1,%2,%3}, [%4];"
                 : "=r"(r0), "=r"(r1), "=r"(r2), "=r"(r3) : "r"(addr));
}

__device__ __forceinline__ void mma_fp16(float* d, uint32_t a0, uint32_t a1,
                                         uint32_t a2, uint32_t a3,
                                         uint32_t b0, uint32_t b1) {
    asm volatile(
        "mma.sync.aligned.m16n8k16.row.col.f32.f16.f16.f32 "
        "{%0,%1,%2,%3}, {%4,%5,%6,%7}, {%8,%9}, {%0,%1,%2,%3};"
        : "+f"(d[0]), "+f"(d[1]), "+f"(d[2]), "+f"(d[3])
        : "r"(a0), "r"(a1), "r"(a2), "r"(a3), "r"(b0), "r"(b1));
}

__device__ __forceinline__ void cp16(uint32_t saddr, const void* g) {
    asm volatile("cp.async.ca.shared.global [%0], [%1], 16;"
                 :: "r"(saddr), "l"(g));
}
#define CP_COMMIT()  asm volatile("cp.async.commit_group;" ::: "memory")
#define CP_WAIT(N)   asm volatile("cp.async.wait_group %0;" :: "n"(N) : "memory")

// ---------------------------------------------------------------------------
__global__ void zero_kernel(float* p, int n) {
    int i = blockIdx.x * blockDim.x + threadIdx.x;
    if (i < n) p[i] = 0.0f;
}

// Wt[n][k] = fp16(W[k][n])
__global__ void transpose16(const float* __restrict__ W, __half* __restrict__ T, int K, int N) {
    int idx = blockIdx.x * blockDim.x + threadIdx.x;
    if (idx >= K * N) return;
    int k = idx / N, n = idx % N;
    T[(size_t)n * K + k] = __float2half_rn(W[idx]);
}

// ---------------------------------------------------------------------------
// Fused 2-layer MLP, one CTA per 128-row block.
//   X   = fp16([Af1 | Af2] concat at col Ksplit)      (smem, K1 cols)
//   H   = relu(X * B1^T + b1)                          (smem, 128x512 fp16)
//   Z   = H * B2^T + b2                                (registers, 128x128)
// MODE 0: Gi_out = Z (fp32)
// MODE 1: v = sigmoid(gate) * Z; segmented-sum over sorted gidx -> atomicAdd Rout
//
// 8 warps (2M x 4N), warp tile 64x32, K-chunk 32, 3-stage cp.async for weights.
// smem: X chunks (K1/32 x 8KB) | H chunks (16 x 8KB) | stages (3 x 8KB)
// ---------------------------------------------------------------------------
template<int K1, int MODE>
__global__ __launch_bounds__(256, 1)
void fused_mlp(const float* __restrict__ Af1, const float* __restrict__ Af2,
               int Ksplit,
               const __half* __restrict__ B1, const float* __restrict__ b1,
               const __half* __restrict__ B2, const float* __restrict__ b2,
               float* __restrict__ Gi_out,
               const float* __restrict__ gate, const int* __restrict__ gidx,
               float* __restrict__ Rout, int M)
{
    constexpr int XC = K1 / 32;          // X k-chunks
    extern __shared__ char smem_raw[];
    const uint32_t sb = smem_to_u32(smem_raw);
    const uint32_t base = (sb + 1023) & ~1023u;
    char* basep = smem_raw + (base - sb);

    const uint32_t Xa = base;                    // X chunks
    const uint32_t Ha = base + XC * 8192;        // H chunks (16)
    const uint32_t Sa = Ha + 16 * 8192;          // 3 weight stages
    const int Hoff = XC * 8192;

    const int tid  = threadIdx.x;
    const int wid  = tid >> 5;
    const int lane = tid & 31;
    const int wm = wid & 1;
    const int wn = wid >> 1;
    const int m0 = blockIdx.x * 128;
    const int lr = lane & 7;
    const int q  = lane >> 3;
    const int g  = lane >> 2, tig = lane & 3;

    // ---------------- X staging: fp32 -> fp16, swizzled chunks ----------------
    {
        constexpr int COL4 = K1 / 4;
#pragma unroll
        for (int i = 0; i < (128 * COL4) / 256; i++) {
            int idx = tid + i * 256;
            int r = idx / COL4;
            int col = (idx % COL4) * 4;
            const float* src = (col < Ksplit) ? Af1 : Af2;
            int kb = (col < Ksplit) ? col : col - Ksplit;
            float4 v = make_float4(0.f, 0.f, 0.f, 0.f);
            if (m0 + r < M)
                v = *reinterpret_cast<const float4*>(src + (size_t)(m0 + r) * 128 + kb);
            __half2 p0 = __halves2half2(__float2half_rn(v.x), __float2half_rn(v.y));
            __half2 p1 = __halves2half2(__float2half_rn(v.z), __float2half_rn(v.w));
            int ch = col >> 5, cb = col & 31;
            uint32_t o = SWZ64((r << 6) + (cb << 1));
            *reinterpret_cast<__half2*>(basep + ch * 8192 + o)     = p0;
            *reinterpret_cast<__half2*>(basep + ch * 8192 + o + 4) = p1;
        }
    }

    float acc[4][4][4];

    // weight-stage loader: chunk kc of rows [nb0, nb0+128) of Bsrc[ldb-strided]
    auto load_B = [&](const __half* Bsrc, int ldb, int nb0, int kc, int s) {
        const int k0 = kc << 5;
#pragma unroll
        for (int i = 0; i < 2; i++) {
            int idx = tid + (i << 8);
            int r = idx >> 2, c16 = idx & 3;
            cp16(Sa + s * 8192 + SWZ64((r << 6) + (c16 << 4)),
                 Bsrc + (size_t)(nb0 + r) * ldb + k0 + (c16 << 3));
        }
        CP_COMMIT();
    };

    auto compute = [&](uint32_t As, uint32_t Bs) {
#pragma unroll
        for (int s = 0; s < 2; s++) {
            const int bc = s << 5;
            uint32_t bf[8];
#pragma unroll
            for (int p = 0; p < 2; p++) {
                int nrow = (wn << 5) + (p << 4) + ((q >> 1) << 3) + lr;
                uint32_t o = SWZ64((nrow << 6) + bc + ((q & 1) << 4));
                ldmatrix_x4(bf[p * 4 + 0], bf[p * 4 + 1], bf[p * 4 + 2], bf[p * 4 + 3], Bs + o);
            }
#pragma unroll
            for (int mt = 0; mt < 4; mt++) {
                int mrow = (wm << 6) + (mt << 4) + ((q & 1) << 3) + lr;
                uint32_t o = SWZ64((mrow << 6) + bc + ((q >> 1) << 4));
                uint32_t a0, a1, a2, a3;
                ldmatrix_x4(a0, a1, a2, a3, As + o);
#pragma unroll
                for (int nt = 0; nt < 4; nt++) {
                    int bi = (nt >> 1) * 4 + (nt & 1) * 2;
                    mma_fp16(acc[mt][nt], a0, a1, a2, a3, bf[bi], bf[bi + 1]);
                }
            }
        }
    };

    // pipelined GEMM over KC chunks: A resident at Aa, B streamed
    auto run_gemm = [&](uint32_t Aa, const __half* Bsrc, int ldb, int nb0, int KC) {
#pragma unroll
        for (int a = 0; a < 4; a++)
#pragma unroll
            for (int b = 0; b < 4; b++)
#pragma unroll
                for (int d = 0; d < 4; d++) acc[a][b][d] = 0.0f;
        __syncthreads();                       // stages / A safe to (re)use
        load_B(Bsrc, ldb, nb0, 0, 0);
        if (KC > 1) load_B(Bsrc, ldb, nb0, 1, 1);
        for (int kc = 0; kc < KC; kc++) {
            if (kc + 1 < KC) { CP_WAIT(1); } else { CP_WAIT(0); }
            __syncthreads();
            if (kc + 2 < KC) load_B(Bsrc, ldb, nb0, kc + 2, (kc + 2) % 3);
            compute(Aa + kc * 8192, Sa + (kc % 3) * 8192);
        }
    };

    // ---------------- phase 1: H = relu(X * B1^T + b1), 4 n-chunks ----------------
#pragma unroll 1
    for (int nc = 0; nc < 4; nc++) {
        run_gemm(Xa, B1, K1, nc * 128, XC);
        // epilogue -> H smem (fp16, swizzled chunks)
#pragma unroll
        for (int mt = 0; mt < 4; mt++) {
#pragma unroll
            for (int hf = 0; hf < 2; hf++) {
                int lrow = (wm << 6) + (mt << 4) + g + (hf << 3);
#pragma unroll
                for (int nt = 0; nt < 4; nt++) {
                    int colw = (wn << 5) + (nt << 3) + (tig << 1);   // col within 128-chunk
                    int col = nc * 128 + colw;
                    float v0 = fmaxf(acc[mt][nt][hf * 2 + 0] + __ldg(b1 + col), 0.0f);
                    float v1 = fmaxf(acc[mt][nt][hf * 2 + 1] + __ldg(b1 + col + 1), 0.0f);
                    int hc = (col >> 5);
                    int cb = col & 31;
                    uint32_t o = SWZ64((lrow << 6) + (cb << 1));
                    *reinterpret_cast<__half2*>(basep + Hoff + hc * 8192 + o) =
                        __halves2half2(__float2half_rn(v0), __float2half_rn(v1));
                }
            }
        }
    }

    // ---------------- phase 2: Z = H * B2^T + b2 (K=512, 16 chunks) ----------------
    run_gemm(Ha, B2, 512, 0, 16);

    if (MODE == 0) {
#pragma unroll
        for (int mt = 0; mt < 4; mt++) {
#pragma unroll
            for (int hf = 0; hf < 2; hf++) {
                int row = m0 + (wm << 6) + (mt << 4) + g + (hf << 3);
                if (row >= M) continue;
#pragma unroll
                for (int nt = 0; nt < 4; nt++) {
                    int col = (wn << 5) + (nt << 3) + (tig << 1);
                    float v0 = acc[mt][nt][hf * 2 + 0] + __ldg(b2 + col);
                    float v1 = acc[mt][nt][hf * 2 + 1] + __ldg(b2 + col + 1);
                    *reinterpret_cast<float2*>(Gi_out + (size_t)row * GDIM + col) = make_float2(v0, v1);
                }
            }
        }
    } else {
        __syncthreads();     // H region dead -> reuse as Dts
        float* Dts = reinterpret_cast<float*>(basep + Hoff);
#pragma unroll
        for (int mt = 0; mt < 4; mt++) {
#pragma unroll
            for (int hf = 0; hf < 2; hf++) {
                int lrow = (wm << 6) + (mt << 4) + g + (hf << 3);
                int row = m0 + lrow;
                if (row >= M) continue;
#pragma unroll
                for (int nt = 0; nt < 4; nt++) {
                    int col = (wn << 5) + (nt << 3) + (tig << 1);
                    float v0 = acc[mt][nt][hf * 2 + 0] + __ldg(b2 + col);
                    float v1 = acc[mt][nt][hf * 2 + 1] + __ldg(b2 + col + 1);
                    float g0 = __ldg(gate + (size_t)row * GDIM + col);
                    float g1 = __ldg(gate + (size_t)row * GDIM + col + 1);
                    float s0 = 1.0f / (1.0f + __expf(-g0));
                    float s1 = 1.0f / (1.0f + __expf(-g1));
                    *reinterpret_cast<float2*>(Dts + lrow * 132 + col) = make_float2(s0 * v0, s1 * v1);
                }
            }
        }
        __syncthreads();

        const int tx = tid & 15, ty = tid >> 4;
        const int tm = ty * 8, tn = tx * 8;
        int cur = -1;
        float run[8];
#pragma unroll
        for (int j = 0; j < 8; j++) run[j] = 0.0f;
        for (int i = 0; i < 8; i++) {
            int r = m0 + tm + i;
            if (r >= M) break;
            int gg = gidx[r];
            if (gg != cur) {
                if (cur >= 0) {
#pragma unroll
                    for (int j = 0; j < 8; j++)
                        atomicAdd(&Rout[(size_t)cur * GDIM + tn + j], run[j]);
                }
                cur = gg;
#pragma unroll
                for (int j = 0; j < 8; j++) run[j] = 0.0f;
            }
#pragma unroll
            for (int j = 0; j < 8; j++)
                run[j] += Dts[(tm + i) * 132 + tn + j];
        }
        if (cur >= 0) {
#pragma unroll
            for (int j = 0; j < 8; j++)
                atomicAdd(&Rout[(size_t)cur * GDIM + tn + j], run[j]);
        }
    }
}

// ---------------------------------------------------------------------------
extern "C" void kernel_launch(void* const* d_in, const int* in_sizes, int n_in,
                              void* d_out, int out_size)
{
    const float* h_T  = (const float*)d_in[0];
    const float* h_0  = (const float*)d_in[1];
    const int*   gidx = (const int*)d_in[2];     // int32 (JAX x64 disabled)
    const float* Wi1  = (const float*)d_in[3];
    const float* bi1  = (const float*)d_in[4];
    const float* Wi2  = (const float*)d_in[5];
    const float* bi2  = (const float*)d_in[6];
    const float* Wj1  = (const float*)d_in[7];
    const float* bj1  = (const float*)d_in[8];
    const float* Wj2  = (const float*)d_in[9];
    const float* bj2  = (const float*)d_in[10];
    float* R = (float*)d_out;

    const int M = in_sizes[0] / 128;
    const int mt = (M + 127) / 128;

    __half *Wi1t, *Wi2t, *Wj1t, *Wj2t;
    float* Gi;
    cudaGetSymbolAddress((void**)&Gi,   g_Gi);
    cudaGetSymbolAddress((void**)&Wi1t, g_Wi1t);
    cudaGetSymbolAddress((void**)&Wi2t, g_Wi2t);
    cudaGetSymbolAddress((void**)&Wj1t, g_Wj1t);
    cudaGetSymbolAddress((void**)&Wj2t, g_Wj2t);

    const int SM1 = 1024 + (8 + 16 + 3) * 8192;   // 222208 (K1=256)
    const int SM2 = 1024 + (4 + 16 + 3) * 8192;   // 189440 (K1=128)
    cudaFuncSetAttribute(fused_mlp<256,0>, cudaFuncAttributeMaxDynamicSharedMemorySize, SM1);
    cudaFuncSetAttribute(fused_mlp<128,1>, cudaFuncAttributeMaxDynamicSharedMemorySize, SM2);

    // prep: weight transposes (tiny), output zero
    transpose16<<<(256 * 512 + 255) / 256, 256>>>(Wi1, Wi1t, 256, 512);
    transpose16<<<(512 * 128 + 255) / 256, 256>>>(Wi2, Wi2t, 512, 128);
    transpose16<<<(128 * 512 + 255) / 256, 256>>>(Wj1, Wj1t, 128, 512);
    transpose16<<<(512 * 128 + 255) / 256, 256>>>(Wj2, Wj2t, 512, 128);
    zero_kernel<<<(out_size + 255) / 256, 256>>>(R, out_size);

    // FK1: Gi = (relu([h_T|h_0] Wi1 + bi1)) Wi2 + bi2
    fused_mlp<256,0><<<mt, 256, SM1>>>(h_T, h_0, 128, Wi1t, bi1, Wi2t, bi2,
                                       Gi, nullptr, nullptr, nullptr, M);

    // FK2: R += segsum(sigmoid(Gi) * ((relu(h_T Wj1 + bj1)) Wj2 + bj2))
    fused_mlp<128,1><<<mt, 256, SM2>>>(h_T, h_T, 128, Wj1t, bj1, Wj2t, bj2,
                                       nullptr, Gi, gidx, R, M);
}

// round 15
// speedup vs baseline: 5.8074x; 1.2854x over previous
#include <cuda_runtime.h>
#include <cuda_fp16.h>
#include <cstdint>
#include <math.h>

#define MAX_NODES 200000
#define GDIM 128

// ---------------------------------------------------------------------------
// Pre-transposed fp16 weights: Wt[n][k] = W[k][n]  (__device__ globals)
// ---------------------------------------------------------------------------
__device__ __align__(16) __half g_Wi1t[512 * 256];
__device__ __align__(16) __half g_Wi2t[128 * 512];
__device__ __align__(16) __half g_Wj1t[512 * 128];
__device__ __align__(16) __half g_Wj2t[128 * 512];

// ---------------------------------------------------------------------------
__device__ __forceinline__ uint32_t smem_to_u32(const void* p) {
    uint32_t a;
    asm("{ .reg .u64 t; cvta.to.shared.u64 t, %1; cvt.u32.u64 %0, t; }" : "=r"(a) : "l"(p));
    return a;
}
#define SWZ64(o) ((o) ^ (((o) >> 3) & 0x30))

__device__ __forceinline__ void ldmatrix_x4(uint32_t& r0, uint32_t& r1,
                                            uint32_t& r2, uint32_t& r3, uint32_t addr) {
    asm volatile("ldmatrix.sync.aligned.m8n8.x4.shared.b16 {%0,%1,%2,%3}, [%4];"
                 : "=r"(r0), "=r"(r1), "=r"(r2), "=r"(r3) : "r"(addr));
}

__device__ __forceinline__ void mma_fp16(float* d, uint32_t a0, uint32_t a1,
                                         uint32_t a2, uint32_t a3,
                                         uint32_t b0, uint32_t b1) {
    asm volatile(
        "mma.sync.aligned.m16n8k16.row.col.f32.f16.f16.f32 "
        "{%0,%1,%2,%3}, {%4,%5,%6,%7}, {%8,%9}, {%0,%1,%2,%3};"
        : "+f"(d[0]), "+f"(d[1]), "+f"(d[2]), "+f"(d[3])
        : "r"(a0), "r"(a1), "r"(a2), "r"(a3), "r"(b0), "r"(b1));
}

__device__ __forceinline__ void cp16(uint32_t saddr, const void* g) {
    asm volatile("cp.async.ca.shared.global [%0], [%1], 16;"
                 :: "r"(saddr), "l"(g));
}
#define CP_COMMIT()  asm volatile("cp.async.commit_group;" ::: "memory")
#define CP_WAIT(N)   asm volatile("cp.async.wait_group %0;" :: "n"(N) : "memory")

// ---------------------------------------------------------------------------
// Prep: zero output + all 4 weight transposes in ONE launch.
// ---------------------------------------------------------------------------
__global__ void prep_kernel(const float* __restrict__ Wi1, const float* __restrict__ Wi2,
                            const float* __restrict__ Wj1, const float* __restrict__ Wj2,
                            __half* __restrict__ Wi1t, __half* __restrict__ Wi2t,
                            __half* __restrict__ Wj1t, __half* __restrict__ Wj2t,
                            float* __restrict__ R, int rn)
{
    int i = blockIdx.x * blockDim.x + threadIdx.x;
    if (i < rn) R[i] = 0.0f;
    // Wi1: 256x512
    if (i < 256 * 512) {
        int k = i / 512, n = i % 512;
        Wi1t[(size_t)n * 256 + k] = __float2half_rn(Wi1[i]);
    }
    // Wi2: 512x128
    if (i < 512 * 128) {
        int k = i / 128, n = i % 128;
        Wi2t[(size_t)n * 512 + k] = __float2half_rn(Wi2[i]);
        // Wj2: 512x128
        Wj2t[(size_t)n * 512 + k] = __float2half_rn(Wj2[i]);
        // Wj1: 128x512 (same element count)
        int k2 = i / 512, n2 = i % 512;
        Wj1t[(size_t)n2 * 128 + k2] = __float2half_rn(Wj1[i]);
    }
}

// ---------------------------------------------------------------------------
// Mega-kernel: one CTA per 128-row block runs the entire readout.
//   X  = fp16([h_T | h_0])                       smem, 8 chunks (h_T = 0..3)
//   H  = relu(X * Wi1^T + bi1)                   smem, 16 chunks
//   Zi = H * Wi2^T + bi2 ; gate = sigmoid(Zi)    registers (64 fp32)
//   H  = relu(h_T * Wj1^T + bj1)                 smem (overwrite)
//   Zj = H * Wj2^T + bj2 ; v = gate * Zj
//   R += segmented_sum(v) over sorted gidx       sparse atomics
// 8 warps (2M x 4N), warp tile 64x32, K-chunk 32, 3-stage cp.async weights.
// ---------------------------------------------------------------------------
#define SMEM_DYN (1024 + (8 + 16 + 3) * 8192)   // 222208

__global__ __launch_bounds__(256, 1)
void mega_mlp(const float* __restrict__ hT, const float* __restrict__ h0,
              const __half* __restrict__ Wi1t, const float* __restrict__ bi1,
              const __half* __restrict__ Wi2t, const float* __restrict__ bi2,
              const __half* __restrict__ Wj1t, const float* __restrict__ bj1,
              const __half* __restrict__ Wj2t, const float* __restrict__ bj2,
              const int* __restrict__ gidx, float* __restrict__ Rout, int M)
{
    extern __shared__ char smem_raw[];
    const uint32_t sb = smem_to_u32(smem_raw);
    const uint32_t base = (sb + 1023) & ~1023u;
    char* basep = smem_raw + (base - sb);

    const uint32_t Xa = base;                 // 8 chunks: [h_T(4) | h_0(4)]
    const uint32_t Ha = base + 8 * 8192;      // 16 chunks
    const uint32_t Sa = Ha + 16 * 8192;       // 3 weight stages
    const int Hoff = 8 * 8192;

    const int tid  = threadIdx.x;
    const int wid  = tid >> 5;
    const int lane = tid & 31;
    const int wm = wid & 1;
    const int wn = wid >> 1;
    const int m0 = blockIdx.x * 128;
    const int lr = lane & 7;
    const int q  = lane >> 3;
    const int g  = lane >> 2, tig = lane & 3;

    // ---------------- X staging: fp32 -> fp16, swizzled chunks ----------------
#pragma unroll
    for (int i = 0; i < 32; i++) {           // 128 rows x 64 float4
        int idx = tid + i * 256;
        int r = idx >> 6;
        int col = (idx & 63) << 2;           // 0..252
        const float* src = (col < 128) ? hT : h0;
        int kb = (col < 128) ? col : col - 128;
        float4 v = make_float4(0.f, 0.f, 0.f, 0.f);
        if (m0 + r < M)
            v = *reinterpret_cast<const float4*>(src + (size_t)(m0 + r) * 128 + kb);
        __half2 p0 = __halves2half2(__float2half_rn(v.x), __float2half_rn(v.y));
        __half2 p1 = __halves2half2(__float2half_rn(v.z), __float2half_rn(v.w));
        int ch = col >> 5, cb = col & 31;
        uint32_t o = SWZ64((r << 6) + (cb << 1));
        *reinterpret_cast<__half2*>(basep + ch * 8192 + o)     = p0;
        *reinterpret_cast<__half2*>(basep + ch * 8192 + o + 4) = p1;
    }

    float acc[4][4][4];
    float gate[4][4][4];

    auto load_B = [&](const __half* Bsrc, int ldb, int nb0, int kc, int s) {
        const int k0 = kc << 5;
#pragma unroll
        for (int i = 0; i < 2; i++) {
            int idx = tid + (i << 8);
            int r = idx >> 2, c16 = idx & 3;
            cp16(Sa + s * 8192 + SWZ64((r << 6) + (c16 << 4)),
                 Bsrc + (size_t)(nb0 + r) * ldb + k0 + (c16 << 3));
        }
        CP_COMMIT();
    };

    auto compute = [&](uint32_t As, uint32_t Bs) {
#pragma unroll
        for (int s = 0; s < 2; s++) {
            const int bc = s << 5;
            uint32_t bf[8];
#pragma unroll
            for (int p = 0; p < 2; p++) {
                int nrow = (wn << 5) + (p << 4) + ((q >> 1) << 3) + lr;
                uint32_t o = SWZ64((nrow << 6) + bc + ((q & 1) << 4));
                ldmatrix_x4(bf[p * 4 + 0], bf[p * 4 + 1], bf[p * 4 + 2], bf[p * 4 + 3], Bs + o);
            }
#pragma unroll
            for (int mt = 0; mt < 4; mt++) {
                int mrow = (wm << 6) + (mt << 4) + ((q & 1) << 3) + lr;
                uint32_t o = SWZ64((mrow << 6) + bc + ((q >> 1) << 4));
                uint32_t a0, a1, a2, a3;
                ldmatrix_x4(a0, a1, a2, a3, As + o);
#pragma unroll
                for (int nt = 0; nt < 4; nt++) {
                    int bi = (nt >> 1) * 4 + (nt & 1) * 2;
                    mma_fp16(acc[mt][nt], a0, a1, a2, a3, bf[bi], bf[bi + 1]);
                }
            }
        }
    };

    // pipelined GEMM over KC chunks: A resident at Aa, B streamed
    auto run_gemm = [&](uint32_t Aa, const __half* Bsrc, int ldb, int nb0, int KC) {
#pragma unroll
        for (int a = 0; a < 4; a++)
#pragma unroll
            for (int b = 0; b < 4; b++)
#pragma unroll
                for (int d = 0; d < 4; d++) acc[a][b][d] = 0.0f;
        __syncthreads();
        load_B(Bsrc, ldb, nb0, 0, 0);
        if (KC > 1) load_B(Bsrc, ldb, nb0, 1, 1);
        for (int kc = 0; kc < KC; kc++) {
            if (kc + 1 < KC) { CP_WAIT(1); } else { CP_WAIT(0); }
            __syncthreads();
            if (kc + 2 < KC) load_B(Bsrc, ldb, nb0, kc + 2, (kc + 2) % 3);
            compute(Aa + kc * 8192, Sa + (kc % 3) * 8192);
        }
    };

    // layer-1 (hidden): H = relu(A * B1^T + b1) over 4 n-chunks of 128
    auto layer1 = [&](const __half* B1, const float* b1, int KC1) {
#pragma unroll 1
        for (int nc = 0; nc < 4; nc++) {
            run_gemm(Xa, B1, KC1 << 5, nc * 128, KC1);
#pragma unroll
            for (int mt = 0; mt < 4; mt++) {
#pragma unroll
                for (int hf = 0; hf < 2; hf++) {
                    int lrow = (wm << 6) + (mt << 4) + g + (hf << 3);
#pragma unroll
                    for (int nt = 0; nt < 4; nt++) {
                        int col = nc * 128 + (wn << 5) + (nt << 3) + (tig << 1);
                        float v0 = fmaxf(acc[mt][nt][hf * 2 + 0] + __ldg(b1 + col), 0.0f);
                        float v1 = fmaxf(acc[mt][nt][hf * 2 + 1] + __ldg(b1 + col + 1), 0.0f);
                        int hc = col >> 5, cb = col & 31;
                        uint32_t o = SWZ64((lrow << 6) + (cb << 1));
                        *reinterpret_cast<__half2*>(basep + Hoff + hc * 8192 + o) =
                            __halves2half2(__float2half_rn(v0), __float2half_rn(v1));
                    }
                }
            }
        }
    };

    // ============ i-net ============
    layer1(Wi1t, bi1, 8);                       // H = relu(X Wi1 + bi1), K=256
    run_gemm(Ha, Wi2t, 512, 0, 16);             // Zi = H Wi2
#pragma unroll
    for (int mt = 0; mt < 4; mt++)
#pragma unroll
        for (int nt = 0; nt < 4; nt++)
#pragma unroll
            for (int d = 0; d < 4; d++) {
                int col = (wn << 5) + (nt << 3) + (tig << 1) + (d & 1);
                float z = acc[mt][nt][d] + __ldg(bi2 + col);
                gate[mt][nt][d] = 1.0f / (1.0f + __expf(-z));
            }

    // ============ j-net ============
    layer1(Wj1t, bj1, 4);                       // H = relu(h_T Wj1 + bj1), K=128
    run_gemm(Ha, Wj2t, 512, 0, 16);             // Zj = H Wj2

    // ============ gated product + segmented reduction ============
    __syncthreads();                            // H region dead -> Dts
    float* Dts = reinterpret_cast<float*>(basep + Hoff);
#pragma unroll
    for (int mt = 0; mt < 4; mt++) {
#pragma unroll
        for (int hf = 0; hf < 2; hf++) {
            int lrow = (wm << 6) + (mt << 4) + g + (hf << 3);
            if (m0 + lrow >= M) continue;
#pragma unroll
            for (int nt = 0; nt < 4; nt++) {
                int col = (wn << 5) + (nt << 3) + (tig << 1);
                float v0 = (acc[mt][nt][hf * 2 + 0] + __ldg(bj2 + col))     * gate[mt][nt][hf * 2 + 0];
                float v1 = (acc[mt][nt][hf * 2 + 1] + __ldg(bj2 + col + 1)) * gate[mt][nt][hf * 2 + 1];
                *reinterpret_cast<float2*>(Dts + lrow * 132 + col) = make_float2(v0, v1);
            }
        }
    }
    __syncthreads();

    const int tx = tid & 15, ty = tid >> 4;
    const int tm = ty * 8, tn = tx * 8;
    int cur = -1;
    float run[8];
#pragma unroll
    for (int j = 0; j < 8; j++) run[j] = 0.0f;
    for (int i = 0; i < 8; i++) {
        int r = m0 + tm + i;
        if (r >= M) break;
        int gg = gidx[r];
        if (gg != cur) {
            if (cur >= 0) {
#pragma unroll
                for (int j = 0; j < 8; j++)
                    atomicAdd(&Rout[(size_t)cur * GDIM + tn + j], run[j]);
            }
            cur = gg;
#pragma unroll
            for (int j = 0; j < 8; j++) run[j] = 0.0f;
        }
#pragma unroll
        for (int j = 0; j < 8; j++)
            run[j] += Dts[(tm + i) * 132 + tn + j];
    }
    if (cur >= 0) {
#pragma unroll
        for (int j = 0; j < 8; j++)
            atomicAdd(&Rout[(size_t)cur * GDIM + tn + j], run[j]);
    }
}

// ---------------------------------------------------------------------------
extern "C" void kernel_launch(void* const* d_in, const int* in_sizes, int n_in,
                              void* d_out, int out_size)
{
    const float* h_T  = (const float*)d_in[0];
    const float* h_0  = (const float*)d_in[1];
    const int*   gidx = (const int*)d_in[2];     // int32 (JAX x64 disabled)
    const float* Wi1  = (const float*)d_in[3];
    const float* bi1  = (const float*)d_in[4];
    const float* Wi2  = (const float*)d_in[5];
    const float* bi2  = (const float*)d_in[6];
    const float* Wj1  = (const float*)d_in[7];
    const float* bj1  = (const float*)d_in[8];
    const float* Wj2  = (const float*)d_in[9];
    const float* bj2  = (const float*)d_in[10];
    float* R = (float*)d_out;

    const int M = in_sizes[0] / 128;
    const int mt = (M + 127) / 128;

    __half *Wi1t, *Wi2t, *Wj1t, *Wj2t;
    cudaGetSymbolAddress((void**)&Wi1t, g_Wi1t);
    cudaGetSymbolAddress((void**)&Wi2t, g_Wi2t);
    cudaGetSymbolAddress((void**)&Wj1t, g_Wj1t);
    cudaGetSymbolAddress((void**)&Wj2t, g_Wj2t);

    cudaFuncSetAttribute(mega_mlp, cudaFuncAttributeMaxDynamicSharedMemorySize, SMEM_DYN);

    // single prep launch: zero R + all weight transposes
    prep_kernel<<<(256 * 512 + 255) / 256, 256>>>(Wi1, Wi2, Wj1, Wj2,
                                                  Wi1t, Wi2t, Wj1t, Wj2t, R, out_size);

    mega_mlp<<<mt, 256, SMEM_DYN>>>(h_T, h_0,
                                    Wi1t, bi1, Wi2t, bi2,
                                    Wj1t, bj1, Wj2t, bj2,
                                    gidx, R, M);
}